// round 4
// baseline (speedup 1.0000x reference)
#include <cuda_runtime.h>
#include <math.h>

#define DIMV 32
#define KN 16
#define NREL 60
#define MAXB 8192

// scratch (device globals: allocation-free)
__device__ float g_uemb [MAXB * DIMV];
__device__ int   g_e1id [MAXB * KN];
__device__ float g_attn0[MAXB * KN];
__device__ int   g_e2id [MAXB * KN * KN];
__device__ float g_attn1[MAXB * KN * KN];

__device__ __forceinline__ float wsum32(float v) {
    #pragma unroll
    for (int o = 16; o > 0; o >>= 1) v += __shfl_xor_sync(0xffffffffu, v, o);
    return v;
}
__device__ __forceinline__ float softmax16(float sc) {
    float m = sc;
    #pragma unroll
    for (int o = 8; o > 0; o >>= 1) m = fmaxf(m, __shfl_xor_sync(0xffffffffu, m, o, 16));
    float e = __expf(sc - m);
    float s = e;
    #pragma unroll
    for (int o = 8; o > 0; o >>= 1) s += __shfl_xor_sync(0xffffffffu, s, o, 16);
    return e / s;
}
__device__ __forceinline__ float sigm(float x) { return 1.f / (1.f + __expf(-x)); }

// ---------------- KA: user emb, udotr, adjacency ids, attention weights ----
__global__ __launch_bounds__(256) void ka_kernel(
    const int*   __restrict__ users,
    const int*   __restrict__ items,
    const float* __restrict__ emb,
    const float* __restrict__ rel,
    const int*   __restrict__ adjE,
    const int*   __restrict__ adjR,
    const int*   __restrict__ hist)
{
    __shared__ float upart[KN][DIMV];
    __shared__ float uemb_s[DIMV];
    __shared__ float udotr_s[64];
    __shared__ int   e1id_s[KN];
    __shared__ int   r0_s[KN];

    const int tid = threadIdx.x, lane = tid & 31, w = tid >> 5;
    const int b = blockIdx.x;
    const int uid  = __ldg(&users[b]);
    const int item = __ldg(&items[b]);

    if (tid < 128) {
        int r = tid >> 3, c = tid & 7;
        int id = __ldg(&hist[uid * KN + r]);
        float4 v = __ldg((const float4*)(emb + (size_t)id * DIMV + c * 4));
        *(float4*)&upart[r][c * 4] = v;
    } else if (tid < 128 + KN) {
        int t = tid - 128;
        int e1 = __ldg(&adjE[(size_t)item * KN + t]);
        e1id_s[t] = e1;
        r0_s[t]   = __ldg(&adjR[(size_t)item * KN + t]);
        g_e1id[b * KN + t] = e1;
    }
    __syncthreads();

    if (tid < DIMV) {
        float s = 0.f;
        #pragma unroll
        for (int r = 0; r < KN; ++r) s += upart[r][tid];
        s *= (1.f / 16.f);
        uemb_s[tid] = s;
        g_uemb[b * DIMV + tid] = s;
    }
    __syncthreads();

    {   // udotr for all 60 relations (8 warps)
        float ul = uemb_s[lane];
        for (int r = w; r < NREL; r += 8) {
            float p = wsum32(ul * __ldg(&rel[r * DIMV + lane]));
            if (lane == 0) udotr_s[r] = p;
        }
    }
    __syncthreads();

    // hop-0 attention (first 32 threads; low 16 meaningful)
    if (tid < 32) {
        float sc = udotr_s[r0_s[tid & 15]];
        float a = softmax16(sc);
        if (tid < KN) g_attn0[b * KN + tid] = a;
    }

    // hop-2 adjacency + hop-1 attention (all 256 threads; one (n,k) each)
    {
        int n = tid >> 4, k = tid & 15;
        size_t base = (size_t)e1id_s[n] * KN + k;
        int e2  = __ldg(&adjE[base]);
        int rid = __ldg(&adjR[base]);
        g_e2id[(size_t)b * 256 + tid] = e2;
        float sc = udotr_s[rid];
        g_attn1[(size_t)b * 256 + tid] = softmax16(sc);
    }
}

// ---------------- KB: gathers + aggregates + matvecs + score --------------
__global__ __launch_bounds__(256, 6) void kb_kernel(
    const int*   __restrict__ items,
    const float* __restrict__ emb,
    const float* __restrict__ W,
    const float* __restrict__ bvec,
    float*       __restrict__ out)
{
    __shared__ __align__(16) float Ws[DIMV * DIMV];
    __shared__ float bs[DIMV];
    __shared__ int   ids_s[256];
    __shared__ float attn_s[256];
    __shared__ int   e1id_s[KN];
    __shared__ float attn0_s[KN];
    __shared__ float uemb_s[DIMV];
    __shared__ __align__(16) float e0s[DIMV];
    __shared__ __align__(16) float e1s[KN][DIMV];
    __shared__ __align__(16) float x1s[KN][DIMV];
    __shared__ float t1s[KN][DIMV];

    const int tid = threadIdx.x, lane = tid & 31, w = tid >> 5;
    const int b = blockIdx.x;

    // ---- stage everything coalesced ----
    ids_s[tid]  = __ldg(&g_e2id [(size_t)b * 256 + tid]);
    attn_s[tid] = __ldg(&g_attn1[(size_t)b * 256 + tid]);
    if (tid < KN) {
        e1id_s[tid]  = __ldg(&g_e1id [b * KN + tid]);
        attn0_s[tid] = __ldg(&g_attn0[b * KN + tid]);
    } else if (tid >= 32 && tid < 64) {
        int t = tid - 32;
        uemb_s[t] = __ldg(&g_uemb[b * DIMV + t]);
        bs[t]     = __ldg(&bvec[t]);
    } else if (tid >= 64 && tid < 72) {
        int c = tid - 64;
        int item = __ldg(&items[b]);
        *(float4*)&e0s[c * 4] = __ldg((const float4*)(emb + (size_t)item * DIMV + c * 4));
    } else if (tid >= 128) {
        int j = tid - 128;
        ((float4*)Ws)[j]       = __ldg(&((const float4*)W)[j]);
        ((float4*)Ws)[j + 128] = __ldg(&((const float4*)W)[j + 128]);
    }
    __syncthreads();

    // ---- gather burst: e1 rows (128 thr) + e2 weighted sum (all, 8 LDG.128) ----
    if (tid < 128) {
        int r = tid >> 3, c = tid & 7;
        *(float4*)&e1s[r][c * 4] =
            __ldg((const float4*)(emb + (size_t)e1id_s[r] * DIMV + c * 4));
    }
    const int n = tid >> 4, c2 = (tid >> 1) & 7, h = tid & 1;
    float4 acc = make_float4(0.f, 0.f, 0.f, 0.f);
    #pragma unroll
    for (int p = 0; p < 8; ++p) {
        int k = h * 8 + p;
        int id  = ids_s[n * KN + k];
        float g = attn_s[n * KN + k];
        float4 v = __ldg((const float4*)(emb + (size_t)id * DIMV + c2 * 4));
        acc.x += g * v.x; acc.y += g * v.y; acc.z += g * v.z; acc.w += g * v.w;
    }
    acc.x += __shfl_xor_sync(0xffffffffu, acc.x, 1);
    acc.y += __shfl_xor_sync(0xffffffffu, acc.y, 1);
    acc.z += __shfl_xor_sync(0xffffffffu, acc.z, 1);
    acc.w += __shfl_xor_sync(0xffffffffu, acc.w, 1);
    __syncthreads();   // e1s ready

    if (h == 0) {
        float4 ev = *(float4*)&e1s[n][c2 * 4];
        float4 x;
        x.x = acc.x + ev.x; x.y = acc.y + ev.y;
        x.z = acc.z + ev.z; x.w = acc.w + ev.w;
        *(float4*)&x1s[n][c2 * 4] = x;
    }
    __syncthreads();   // x1s ready

    // ---- matvecs: warp w handles nodes w, w+8; warp 0 folds in hop-0 x ----
    float t0f = 0.f;
    {
        float xa = x1s[w][lane];
        float xbv = x1s[w + 8][lane];
        float xx = 0.f;
        if (w == 0) {
            float a = 0.f;
            #pragma unroll
            for (int k = 0; k < KN; ++k) a += attn0_s[k] * e1s[k][lane];
            xx = e0s[lane] + a;
        }
        float y0 = bs[lane], y1 = y0, y2 = y0;
        #pragma unroll
        for (int j = 0; j < DIMV; ++j) {
            float wj = Ws[j * DIMV + lane];
            y0 += __shfl_sync(0xffffffffu, xa,  j) * wj;
            y1 += __shfl_sync(0xffffffffu, xbv, j) * wj;
            if (w == 0) y2 += __shfl_sync(0xffffffffu, xx, j) * wj;
        }
        t1s[w][lane]     = sigm(y0);
        t1s[w + 8][lane] = sigm(y1);
        if (w == 0) t0f = sigm(y2);
    }
    __syncthreads();   // t1s ready

    if (w == 0) {
        float a = 0.f;
        #pragma unroll
        for (int k = 0; k < KN; ++k) a += attn0_s[k] * t1s[k][lane];
        float xf = t0f + a;
        float yf = bs[lane];
        #pragma unroll
        for (int j = 0; j < DIMV; ++j)
            yf += __shfl_sync(0xffffffffu, xf, j) * Ws[j * DIMV + lane];
        float f = tanhf(yf);
        float s = wsum32(uemb_s[lane] * f);
        if (lane == 0) out[b] = sigm(s);
    }
}

extern "C" void kernel_launch(void* const* d_in, const int* in_sizes, int n_in,
                              void* d_out, int out_size) {
    const int*   users        = (const int*)  d_in[0];
    const int*   items        = (const int*)  d_in[1];
    const float* entity_emb   = (const float*)d_in[2];
    const float* relation_emb = (const float*)d_in[3];
    const int*   adj_entity   = (const int*)  d_in[4];
    const int*   adj_relation = (const int*)  d_in[5];
    const int*   user_history = (const int*)  d_in[6];
    const float* W            = (const float*)d_in[7];
    const float* b            = (const float*)d_in[8];
    float* out = (float*)d_out;

    int B = in_sizes[0];
    ka_kernel<<<B, 256>>>(users, items, entity_emb, relation_emb,
                          adj_entity, adj_relation, user_history);
    kb_kernel<<<B, 256>>>(items, entity_emb, W, b, out);
}